// round 7
// baseline (speedup 1.0000x reference)
#include <cuda_runtime.h>

// SSIM loss, separable Gaussian (11x11, sigma=1.5), single fused kernel.
//
// Field reduction: with u=x+y, v=x-y and U,V,P,Q = conv(u),conv(v),conv(u^2),conv(v^2):
//   mux^2+muy^2 = (U^2+V^2)/2        2*mu_xy = (U^2-V^2)/2
//   Cxx+Cyy     = (P+Q)/2            2*Cxy   = (P-Q)/2
// -> only 4 conv fields, packed as two f32x2 pairs (U,V) and (P,Q).
//
// Horizontal conv straight from GMEM (aligned float4 windows; branch-free
// interior fast path, predicated edge path) -> smem H-buffer -> vertical conv
// + SSIM epilogue in registers -> fused double-atomic reduction.

#define TW 64
#define TH 32
#define HH 42              // TH + 10 halo rows
#define NTHREADS 256
#define GX 8               // 512/TW
#define GY 16              // 512/TH
#define GZ 48              // B*C
#define NBLOCKS (GX*GY*GZ)

// H-buffer: P1 = (U,V) pairs [HH][64 pairs], P2 = (P,Q) pairs
#define P2_OFF (HH*128)
#define SMEM_FLOATS (2*HH*128)
#define SMEM_BYTES (SMEM_FLOATS*4)      // 43008 B -> 4 CTAs/SM

__device__ double       g_accum;   // zero-init at module load; reset by last block
__device__ unsigned int g_count;

// Gaussian half-window (symmetric: w[t] = w[10-t])
#define W0 0.00102838f
#define W1 0.00759876f
#define W2 0.03600077f
#define W3 0.10936069f
#define W4 0.21300546f
#define W5 0.26601173f
#define KT(t) ((t) < 6 ? (t) : 10 - (t))

__device__ __forceinline__ unsigned long long f2_pack(float lo, float hi) {
    unsigned long long d;
    asm("mov.b64 %0, {%1, %2};" : "=l"(d) : "r"(__float_as_uint(lo)), "r"(__float_as_uint(hi)));
    return d;
}
__device__ __forceinline__ void f2_unpack(unsigned long long v, float& lo, float& hi) {
    unsigned int a, b;
    asm("mov.b64 {%0, %1}, %2;" : "=r"(a), "=r"(b) : "l"(v));
    lo = __uint_as_float(a); hi = __uint_as_float(b);
}
__device__ __forceinline__ unsigned long long f2_fma(unsigned long long a,
                                                     unsigned long long b,
                                                     unsigned long long c) {
    unsigned long long d;
    asm("fma.rn.f32x2 %0, %1, %2, %3;" : "=l"(d) : "l"(a), "l"(b), "l"(c));
    return d;
}
__device__ __forceinline__ unsigned long long f2_mul(unsigned long long a,
                                                     unsigned long long b) {
    unsigned long long d;
    asm("mul.rn.f32x2 %0, %1, %2;" : "=l"(d) : "l"(a), "l"(b));
    return d;
}

__global__ void __launch_bounds__(NTHREADS, 4)
ssim_fused_kernel(const float* __restrict__ X, const float* __restrict__ Y,
                  float* __restrict__ out)
{
    // 6 unique packed weights (symmetry)
    unsigned long long kw2[6];
    kw2[0] = f2_pack(W0, W0); kw2[1] = f2_pack(W1, W1); kw2[2] = f2_pack(W2, W2);
    kw2[3] = f2_pack(W3, W3); kw2[4] = f2_pack(W4, W4); kw2[5] = f2_pack(W5, W5);

    extern __shared__ float Hbuf[];

    const int tid = threadIdx.x;
    const size_t base = (size_t)blockIdx.z << 18;
    const float* xb = X + base;
    const float* yb = Y + base;
    const int gy0 = blockIdx.y * TH - 5;
    const int cbase = blockIdx.x * TW;

    // Block-uniform interior test: interior blocks never touch out-of-image
    // addresses in phase A (rows 27..484, aligned col window within [0,512)).
    const bool interior = (blockIdx.x > 0) & (blockIdx.x < GX - 1) &
                          (blockIdx.y > 0) & (blockIdx.y < GY - 1);

    // ---- Phase A: horizontal conv from GMEM, 2 packed fields ----
    // Item = (halo row, 4-wide output strip). 42 * 16 = 672 items.
    for (int item = tid; item < HH * 16; item += NTHREADS) {
        int row = item >> 4;
        int xs  = (item & 15) << 2;
        int gr  = gy0 + row;
        int a0  = cbase + xs - 8;           // aligned float4 window base

        float xv[20], yv[20];
        if (interior) {
            const float* xr = xb + ((size_t)gr << 9);
            const float* yr = yb + ((size_t)gr << 9);
            #pragma unroll
            for (int q = 0; q < 5; q++) {
                float4 xa = *(const float4*)(xr + a0 + 4 * q);
                float4 ya = *(const float4*)(yr + a0 + 4 * q);
                xv[4*q+0]=xa.x; xv[4*q+1]=xa.y; xv[4*q+2]=xa.z; xv[4*q+3]=xa.w;
                yv[4*q+0]=ya.x; yv[4*q+1]=ya.y; yv[4*q+2]=ya.z; yv[4*q+3]=ya.w;
            }
        } else {
            bool rok = ((unsigned)gr < 512u);
            const float* xr = xb + ((size_t)(gr & 511) << 9);
            const float* yr = yb + ((size_t)(gr & 511) << 9);
            #pragma unroll
            for (int q = 0; q < 5; q++) {
                int c = a0 + 4 * q;
                float4 xa, ya;
                if (rok && (unsigned)c < 512u) {
                    xa = *(const float4*)(xr + c);
                    ya = *(const float4*)(yr + c);
                } else {
                    xa = make_float4(0.f, 0.f, 0.f, 0.f);
                    ya = xa;
                }
                xv[4*q+0]=xa.x; xv[4*q+1]=xa.y; xv[4*q+2]=xa.z; xv[4*q+3]=xa.w;
                yv[4*q+0]=ya.x; yv[4*q+1]=ya.y; yv[4*q+2]=ya.z; yv[4*q+3]=ya.w;
            }
        }

        unsigned long long Puv[4], Pqq[4];
        #pragma unroll
        for (int k = 0; k < 4; k++) { Puv[k] = 0ull; Pqq[k] = 0ull; }

        // output col c0+k uses input index j = k + t + 3, t in [0,10]
        #pragma unroll
        for (int j = 3; j < 17; j++) {
            float u = xv[j] + yv[j];
            float v = xv[j] - yv[j];
            unsigned long long p = f2_pack(u, v);     // (u, v)
            unsigned long long q = f2_mul(p, p);      // (u^2, v^2)
            #pragma unroll
            for (int k = 0; k < 4; k++) {
                int t = j - 3 - k;
                if (t >= 0 && t < 11) {
                    Puv[k] = f2_fma(kw2[KT(t)], p, Puv[k]);
                    Pqq[k] = f2_fma(kw2[KT(t)], q, Pqq[k]);
                }
            }
        }

        float* p1 = Hbuf + row * 128 + xs * 2;      // pair-interleaved
        *(ulonglong2*)(p1)     = make_ulonglong2(Puv[0], Puv[1]);
        *(ulonglong2*)(p1 + 4) = make_ulonglong2(Puv[2], Puv[3]);
        float* p2 = p1 + P2_OFF;
        *(ulonglong2*)(p2)     = make_ulonglong2(Pqq[0], Pqq[1]);
        *(ulonglong2*)(p2 + 4) = make_ulonglong2(Pqq[2], Pqq[3]);
    }
    __syncthreads();

    // ---- Phase B: vertical conv (8-row strip) + SSIM epilogue ----
    const int col = tid & 63;
    const int r0  = (tid >> 6) << 3;    // 0,8,16,24

    unsigned long long AB[8], CD[8];
    #pragma unroll
    for (int k = 0; k < 8; k++) { AB[k] = 0ull; CD[k] = 0ull; }

    const float* q1 = Hbuf + r0 * 128 + 2 * col;
    #pragma unroll
    for (int j = 0; j < 18; j++) {
        unsigned long long v1 = *(const unsigned long long*)(q1 + j * 128);
        unsigned long long v2 = *(const unsigned long long*)(q1 + j * 128 + P2_OFF);
        #pragma unroll
        for (int k = 0; k < 8; k++) {
            int t = j - k;
            if (t >= 0 && t < 11) {
                AB[k] = f2_fma(kw2[KT(t)], v1, AB[k]);
                CD[k] = f2_fma(kw2[KT(t)], v2, CD[k]);
            }
        }
    }

    float lsum = 0.f;
    #pragma unroll
    for (int k = 0; k < 8; k++) {
        float U2, V2, Pk, Qk;
        unsigned long long sq = f2_mul(AB[k], AB[k]);   // (U^2, V^2)
        f2_unpack(sq, U2, V2);
        f2_unpack(CD[k], Pk, Qk);
        float m2     = 0.5f * (U2 + V2);   // mux^2 + muy^2
        float t1     = 0.5f * (U2 - V2);   // 2*mu_xy
        float Ps     = 0.5f * (Pk + Qk);   // Cxx + Cyy
        float Pd     = 0.5f * (Pk - Qk);   // 2*Cxy
        float sig2   = Pd - t1;            // 2*sigma_xy
        float sigsum = Ps - m2;            // sigma_x2 + sigma_y2
        float num = (t1 + 1e-4f) * (sig2 + 9e-4f);
        float den = (m2 + 1e-4f) * (sigsum + 9e-4f) + 1e-8f;
        lsum += __fdividef(num, den);
    }

    // ---- Block reduction ----
    #pragma unroll
    for (int o = 16; o > 0; o >>= 1)
        lsum += __shfl_xor_sync(0xffffffffu, lsum, o);
    __shared__ float wsum[8];
    if ((tid & 31) == 0) wsum[tid >> 5] = lsum;
    __syncthreads();

    // ---- Fused global reduction: double atomic + arrival counter ----
    if (tid == 0) {
        float s = 0.f;
        #pragma unroll
        for (int w = 0; w < 8; w++) s += wsum[w];
        atomicAdd(&g_accum, (double)s);
        __threadfence();
        unsigned int prev = atomicAdd(&g_count, 1u);
        if (prev == NBLOCKS - 1u) {
            double tot = atomicAdd(&g_accum, 0.0);   // coherent read at L2
            out[0] = (float)(1.0 - tot / 12582912.0);
            // reset for next (graph-replayed) launch
            atomicExch((unsigned long long*)&g_accum, 0ull);
            atomicExch(&g_count, 0u);
        }
    }
}

extern "C" void kernel_launch(void* const* d_in, const int* in_sizes, int n_in,
                              void* d_out, int out_size)
{
    const float* x = (const float*)d_in[0];
    const float* y = (const float*)d_in[1];
    float* out = (float*)d_out;

    cudaFuncSetAttribute(ssim_fused_kernel,
                         cudaFuncAttributeMaxDynamicSharedMemorySize, SMEM_BYTES);
    dim3 grid(GX, GY, GZ);
    ssim_fused_kernel<<<grid, NTHREADS, SMEM_BYTES>>>(x, y, out);
}

// round 9
// speedup vs baseline: 1.0831x; 1.0831x over previous
#include <cuda_runtime.h>

// SSIM loss, separable Gaussian (11x11, sigma=1.5), single fused kernel.
//
// Field reduction: with u=x+y, v=x-y and U,V,P,Q = conv(u),conv(v),conv(u^2),conv(v^2):
//   mux^2+muy^2 = (U^2+V^2)/2        2*mu_xy = (U^2-V^2)/2
//   Cxx+Cyy     = (P+Q)/2            2*Cxy   = (P-Q)/2
//
// VERTICAL-FIRST layout (transposed vs earlier rounds) so every memory access
// is stride-optimal:
//   Phase A: vertical conv. thread = (halo col, 8-row strip); lanes along cols
//            -> coalesced LDG.32; stores one 16B (U,V,P,Q) quad per col ->
//            conflict-free STS.128.
//   Phase B: horizontal conv. warp = 8-col strip, lane = row; Vbuf row stride
//            308 floats (1232B, 20 banks mod 32) -> bandwidth-optimal LDS.128.
// Then SSIM epilogue in registers -> fused double-atomic reduction.

#define TW 64
#define TH 32
#define HC 74              // halo cols = TW + 10
#define NTHREADS 256
#define GX 8               // 512/TW
#define GY 16              // 512/TH
#define GZ 48              // B*C
#define NBLOCKS (GX*GY*GZ)

#define VST 308            // Vbuf row stride in floats (1232 B: 16B-aligned, bank-spread)
#define SMEM_BYTES (TH*VST*4)   // 39424 B

__device__ double       g_accum;   // zero-init at module load; reset by last block
__device__ unsigned int g_count;

// Gaussian half-window (symmetric: w[t] = w[10-t])
#define W0 0.00102838f
#define W1 0.00759876f
#define W2 0.03600077f
#define W3 0.10936069f
#define W4 0.21300546f
#define W5 0.26601173f
#define KT(t) ((t) < 6 ? (t) : 10 - (t))

typedef unsigned long long ull;

__device__ __forceinline__ ull f2_pack(float lo, float hi) {
    ull d;
    asm("mov.b64 %0, {%1, %2};" : "=l"(d) : "r"(__float_as_uint(lo)), "r"(__float_as_uint(hi)));
    return d;
}
__device__ __forceinline__ void f2_unpack(ull v, float& lo, float& hi) {
    unsigned int a, b;
    asm("mov.b64 {%0, %1}, %2;" : "=r"(a), "=r"(b) : "l"(v));
    lo = __uint_as_float(a); hi = __uint_as_float(b);
}
__device__ __forceinline__ ull f2_fma(ull a, ull b, ull c) {
    ull d;
    asm("fma.rn.f32x2 %0, %1, %2, %3;" : "=l"(d) : "l"(a), "l"(b), "l"(c));
    return d;
}
__device__ __forceinline__ ull f2_mul(ull a, ull b) {
    ull d;
    asm("mul.rn.f32x2 %0, %1, %2;" : "=l"(d) : "l"(a), "l"(b));
    return d;
}

__global__ void __launch_bounds__(NTHREADS, 4)
ssim_fused_kernel(const float* __restrict__ X, const float* __restrict__ Y,
                  float* __restrict__ out)
{
    // 6 unique packed weights (symmetry)
    ull kw2[6];
    kw2[0] = f2_pack(W0, W0); kw2[1] = f2_pack(W1, W1); kw2[2] = f2_pack(W2, W2);
    kw2[3] = f2_pack(W3, W3); kw2[4] = f2_pack(W4, W4); kw2[5] = f2_pack(W5, W5);

    extern __shared__ float Vbuf[];   // [TH rows][VST floats]; col c at offset c*4

    const int tid = threadIdx.x;
    const int bx = blockIdx.x, by = blockIdx.y;
    const size_t base = (size_t)blockIdx.z << 18;
    const int gx0 = bx * TW - 5;      // global col of Vbuf col 0
    const bool interior = (bx > 0) & (bx < GX - 1) & (by > 0) & (by < GY - 1);

    // ---- Phase A: vertical conv, 2 packed fields ----
    // Item = (8-row strip s in 0..3, halo col c in 0..73). 296 items.
    for (int item = tid; item < 4 * HC; item += NTHREADS) {
        int s = item / HC;
        int c = item - s * HC;
        int gc = gx0 + c;
        int gr0 = by * TH + s * 8 - 5;    // first input row

        ull Puv[8], Pqq[8];
        #pragma unroll
        for (int k = 0; k < 8; k++) { Puv[k] = 0ull; Pqq[k] = 0ull; }

        if (interior) {
            const float* xp = X + base + ((size_t)gr0 << 9) + gc;
            const float* yp = Y + base + ((size_t)gr0 << 9) + gc;
            #pragma unroll
            for (int j = 0; j < 18; j++) {
                float xj = __ldg(xp + (j << 9));
                float yj = __ldg(yp + (j << 9));
                float u = xj + yj, v = xj - yj;
                ull p = f2_pack(u, v);
                ull q = f2_mul(p, p);
                #pragma unroll
                for (int k = 0; k < 8; k++) {
                    int t = j - k;
                    if (t >= 0 && t < 11) {
                        Puv[k] = f2_fma(kw2[KT(t)], p, Puv[k]);
                        Pqq[k] = f2_fma(kw2[KT(t)], q, Pqq[k]);
                    }
                }
            }
        } else {
            #pragma unroll
            for (int j = 0; j < 18; j++) {
                int gr = gr0 + j;
                bool ok = ((unsigned)gr < 512u) & ((unsigned)gc < 512u);
                size_t off = base + ((size_t)(gr & 511) << 9) + (gc & 511);
                float xj = ok ? __ldg(X + off) : 0.f;
                float yj = ok ? __ldg(Y + off) : 0.f;
                float u = xj + yj, v = xj - yj;
                ull p = f2_pack(u, v);
                ull q = f2_mul(p, p);
                #pragma unroll
                for (int k = 0; k < 8; k++) {
                    int t = j - k;
                    if (t >= 0 && t < 11) {
                        Puv[k] = f2_fma(kw2[KT(t)], p, Puv[k]);
                        Pqq[k] = f2_fma(kw2[KT(t)], q, Pqq[k]);
                    }
                }
            }
        }

        // Store (U,V,P,Q) quad per (row, col); lanes adjacent in c -> conflict-free
        float* vb = Vbuf + (s << 3) * VST + (c << 2);
        #pragma unroll
        for (int k = 0; k < 8; k++)
            *(ulonglong2*)(vb + k * VST) = make_ulonglong2(Puv[k], Pqq[k]);
    }
    __syncthreads();

    // ---- Phase B: horizontal conv (8-col strip) + SSIM epilogue ----
    // warp = strip, lane = row: LDS.128 at row stride 1232B = bank-optimal.
    const int row = tid & 31;
    const int st  = tid >> 5;         // 0..7, output cols 8*st .. 8*st+7

    ull AB[8], CD[8];
    #pragma unroll
    for (int k = 0; k < 8; k++) { AB[k] = 0ull; CD[k] = 0ull; }

    const float* q1 = Vbuf + row * VST + (st << 5);   // col 8*st -> 32 floats
    #pragma unroll
    for (int i = 0; i < 18; i++) {
        ulonglong2 w = *(const ulonglong2*)(q1 + (i << 2));
        #pragma unroll
        for (int k = 0; k < 8; k++) {
            int t = i - k;
            if (t >= 0 && t < 11) {
                AB[k] = f2_fma(kw2[KT(t)], w.x, AB[k]);
                CD[k] = f2_fma(kw2[KT(t)], w.y, CD[k]);
            }
        }
    }

    float lsum = 0.f;
    #pragma unroll
    for (int k = 0; k < 8; k++) {
        float U2, V2, Pk, Qk;
        ull sq = f2_mul(AB[k], AB[k]);   // (U^2, V^2)
        f2_unpack(sq, U2, V2);
        f2_unpack(CD[k], Pk, Qk);
        float m2     = 0.5f * (U2 + V2);   // mux^2 + muy^2
        float t1     = 0.5f * (U2 - V2);   // 2*mu_xy
        float Ps     = 0.5f * (Pk + Qk);   // Cxx + Cyy
        float Pd     = 0.5f * (Pk - Qk);   // 2*Cxy
        float sig2   = Pd - t1;            // 2*sigma_xy
        float sigsum = Ps - m2;            // sigma_x2 + sigma_y2
        float num = (t1 + 1e-4f) * (sig2 + 9e-4f);
        float den = (m2 + 1e-4f) * (sigsum + 9e-4f) + 1e-8f;
        lsum += __fdividef(num, den);
    }

    // ---- Block reduction ----
    #pragma unroll
    for (int o = 16; o > 0; o >>= 1)
        lsum += __shfl_xor_sync(0xffffffffu, lsum, o);
    __shared__ float wsum[8];
    if ((tid & 31) == 0) wsum[tid >> 5] = lsum;
    __syncthreads();

    // ---- Fused global reduction: double atomic + arrival counter ----
    if (tid == 0) {
        float s = 0.f;
        #pragma unroll
        for (int w = 0; w < 8; w++) s += wsum[w];
        atomicAdd(&g_accum, (double)s);
        __threadfence();
        unsigned int prev = atomicAdd(&g_count, 1u);
        if (prev == NBLOCKS - 1u) {
            double tot = atomicAdd(&g_accum, 0.0);   // coherent read at L2
            out[0] = (float)(1.0 - tot / 12582912.0);
            // reset for next (graph-replayed) launch
            atomicExch((unsigned long long*)&g_accum, 0ull);
            atomicExch(&g_count, 0u);
        }
    }
}

extern "C" void kernel_launch(void* const* d_in, const int* in_sizes, int n_in,
                              void* d_out, int out_size)
{
    const float* x = (const float*)d_in[0];
    const float* y = (const float*)d_in[1];
    float* out = (float*)d_out;

    dim3 grid(GX, GY, GZ);
    ssim_fused_kernel<<<grid, NTHREADS, SMEM_BYTES>>>(x, y, out);
}

// round 10
// speedup vs baseline: 1.0873x; 1.0039x over previous
#include <cuda_runtime.h>

// SSIM loss, separable Gaussian (11x11, sigma=1.5), single fused kernel.
//
// Field reduction: with u=x+y, v=x-y and U,V,P,Q = conv(u),conv(v),conv(u^2),conv(v^2):
//   mux^2+muy^2 = (U^2+V^2)/2        2*mu_xy = (U^2-V^2)/2
//   Cxx+Cyy     = (P+Q)/2            2*Cxy   = (P-Q)/2
//
// VERTICAL-FIRST layout (transposed vs earlier rounds) so every memory access
// is stride-optimal:
//   Phase A: vertical conv. thread = (halo col, 8-row strip); lanes along cols
//            -> coalesced LDG.32; stores one 16B (U,V,P,Q) quad per col ->
//            conflict-free STS.128.
//   Phase B: horizontal conv. warp = 8-col strip, lane = row; Vbuf row stride
//            308 floats (1232B, 20 banks mod 32) -> bandwidth-optimal LDS.128.
// Then SSIM epilogue in registers -> fused double-atomic reduction.

#define TW 64
#define TH 32
#define HC 74              // halo cols = TW + 10
#define NTHREADS 256
#define GX 8               // 512/TW
#define GY 16              // 512/TH
#define GZ 48              // B*C
#define NBLOCKS (GX*GY*GZ)

#define VST 308            // Vbuf row stride in floats (1232 B: 16B-aligned, bank-spread)
#define SMEM_BYTES (TH*VST*4)   // 39424 B

__device__ double       g_accum;   // zero-init at module load; reset by last block
__device__ unsigned int g_count;

// Gaussian half-window (symmetric: w[t] = w[10-t])
#define W0 0.00102838f
#define W1 0.00759876f
#define W2 0.03600077f
#define W3 0.10936069f
#define W4 0.21300546f
#define W5 0.26601173f
#define KT(t) ((t) < 6 ? (t) : 10 - (t))

typedef unsigned long long ull;

__device__ __forceinline__ ull f2_pack(float lo, float hi) {
    ull d;
    asm("mov.b64 %0, {%1, %2};" : "=l"(d) : "r"(__float_as_uint(lo)), "r"(__float_as_uint(hi)));
    return d;
}
__device__ __forceinline__ void f2_unpack(ull v, float& lo, float& hi) {
    unsigned int a, b;
    asm("mov.b64 {%0, %1}, %2;" : "=r"(a), "=r"(b) : "l"(v));
    lo = __uint_as_float(a); hi = __uint_as_float(b);
}
__device__ __forceinline__ ull f2_fma(ull a, ull b, ull c) {
    ull d;
    asm("fma.rn.f32x2 %0, %1, %2, %3;" : "=l"(d) : "l"(a), "l"(b), "l"(c));
    return d;
}
__device__ __forceinline__ ull f2_mul(ull a, ull b) {
    ull d;
    asm("mul.rn.f32x2 %0, %1, %2;" : "=l"(d) : "l"(a), "l"(b));
    return d;
}

__global__ void __launch_bounds__(NTHREADS, 4)
ssim_fused_kernel(const float* __restrict__ X, const float* __restrict__ Y,
                  float* __restrict__ out)
{
    // 6 unique packed weights (symmetry)
    ull kw2[6];
    kw2[0] = f2_pack(W0, W0); kw2[1] = f2_pack(W1, W1); kw2[2] = f2_pack(W2, W2);
    kw2[3] = f2_pack(W3, W3); kw2[4] = f2_pack(W4, W4); kw2[5] = f2_pack(W5, W5);

    extern __shared__ float Vbuf[];   // [TH rows][VST floats]; col c at offset c*4

    const int tid = threadIdx.x;
    const int bx = blockIdx.x, by = blockIdx.y;
    const size_t base = (size_t)blockIdx.z << 18;
    const int gx0 = bx * TW - 5;      // global col of Vbuf col 0
    const bool interior = (bx > 0) & (bx < GX - 1) & (by > 0) & (by < GY - 1);

    // ---- Phase A: vertical conv, 2 packed fields ----
    // Item = (8-row strip s in 0..3, halo col c in 0..73). 296 items.
    for (int item = tid; item < 4 * HC; item += NTHREADS) {
        int s = item / HC;
        int c = item - s * HC;
        int gc = gx0 + c;
        int gr0 = by * TH + s * 8 - 5;    // first input row

        ull Puv[8], Pqq[8];
        #pragma unroll
        for (int k = 0; k < 8; k++) { Puv[k] = 0ull; Pqq[k] = 0ull; }

        if (interior) {
            const float* xp = X + base + ((size_t)gr0 << 9) + gc;
            const float* yp = Y + base + ((size_t)gr0 << 9) + gc;
            #pragma unroll
            for (int j = 0; j < 18; j++) {
                float xj = __ldg(xp + (j << 9));
                float yj = __ldg(yp + (j << 9));
                float u = xj + yj, v = xj - yj;
                ull p = f2_pack(u, v);
                ull q = f2_mul(p, p);
                #pragma unroll
                for (int k = 0; k < 8; k++) {
                    int t = j - k;
                    if (t >= 0 && t < 11) {
                        Puv[k] = f2_fma(kw2[KT(t)], p, Puv[k]);
                        Pqq[k] = f2_fma(kw2[KT(t)], q, Pqq[k]);
                    }
                }
            }
        } else {
            #pragma unroll
            for (int j = 0; j < 18; j++) {
                int gr = gr0 + j;
                bool ok = ((unsigned)gr < 512u) & ((unsigned)gc < 512u);
                size_t off = base + ((size_t)(gr & 511) << 9) + (gc & 511);
                float xj = ok ? __ldg(X + off) : 0.f;
                float yj = ok ? __ldg(Y + off) : 0.f;
                float u = xj + yj, v = xj - yj;
                ull p = f2_pack(u, v);
                ull q = f2_mul(p, p);
                #pragma unroll
                for (int k = 0; k < 8; k++) {
                    int t = j - k;
                    if (t >= 0 && t < 11) {
                        Puv[k] = f2_fma(kw2[KT(t)], p, Puv[k]);
                        Pqq[k] = f2_fma(kw2[KT(t)], q, Pqq[k]);
                    }
                }
            }
        }

        // Store (U,V,P,Q) quad per (row, col); lanes adjacent in c -> conflict-free
        float* vb = Vbuf + (s << 3) * VST + (c << 2);
        #pragma unroll
        for (int k = 0; k < 8; k++)
            *(ulonglong2*)(vb + k * VST) = make_ulonglong2(Puv[k], Pqq[k]);
    }
    __syncthreads();

    // ---- Phase B: horizontal conv (8-col strip) + SSIM epilogue ----
    // warp = strip, lane = row: LDS.128 at row stride 1232B = bank-optimal.
    const int row = tid & 31;
    const int st  = tid >> 5;         // 0..7, output cols 8*st .. 8*st+7

    ull AB[8], CD[8];
    #pragma unroll
    for (int k = 0; k < 8; k++) { AB[k] = 0ull; CD[k] = 0ull; }

    const float* q1 = Vbuf + row * VST + (st << 5);   // col 8*st -> 32 floats
    #pragma unroll
    for (int i = 0; i < 18; i++) {
        ulonglong2 w = *(const ulonglong2*)(q1 + (i << 2));
        #pragma unroll
        for (int k = 0; k < 8; k++) {
            int t = i - k;
            if (t >= 0 && t < 11) {
                AB[k] = f2_fma(kw2[KT(t)], w.x, AB[k]);
                CD[k] = f2_fma(kw2[KT(t)], w.y, CD[k]);
            }
        }
    }

    float lsum = 0.f;
    #pragma unroll
    for (int k = 0; k < 8; k++) {
        float U2, V2, Pk, Qk;
        ull sq = f2_mul(AB[k], AB[k]);   // (U^2, V^2)
        f2_unpack(sq, U2, V2);
        f2_unpack(CD[k], Pk, Qk);
        float m2     = 0.5f * (U2 + V2);   // mux^2 + muy^2
        float t1     = 0.5f * (U2 - V2);   // 2*mu_xy
        float Ps     = 0.5f * (Pk + Qk);   // Cxx + Cyy
        float Pd     = 0.5f * (Pk - Qk);   // 2*Cxy
        float sig2   = Pd - t1;            // 2*sigma_xy
        float sigsum = Ps - m2;            // sigma_x2 + sigma_y2
        float num = (t1 + 1e-4f) * (sig2 + 9e-4f);
        float den = (m2 + 1e-4f) * (sigsum + 9e-4f) + 1e-8f;
        lsum += __fdividef(num, den);
    }

    // ---- Block reduction ----
    #pragma unroll
    for (int o = 16; o > 0; o >>= 1)
        lsum += __shfl_xor_sync(0xffffffffu, lsum, o);
    __shared__ float wsum[8];
    if ((tid & 31) == 0) wsum[tid >> 5] = lsum;
    __syncthreads();

    // ---- Fused global reduction: double atomic + arrival counter ----
    if (tid == 0) {
        float s = 0.f;
        #pragma unroll
        for (int w = 0; w < 8; w++) s += wsum[w];
        atomicAdd(&g_accum, (double)s);
        __threadfence();
        unsigned int prev = atomicAdd(&g_count, 1u);
        if (prev == NBLOCKS - 1u) {
            double tot = atomicAdd(&g_accum, 0.0);   // coherent read at L2
            out[0] = (float)(1.0 - tot / 12582912.0);
            // reset for next (graph-replayed) launch
            atomicExch((unsigned long long*)&g_accum, 0ull);
            atomicExch(&g_count, 0u);
        }
    }
}

extern "C" void kernel_launch(void* const* d_in, const int* in_sizes, int n_in,
                              void* d_out, int out_size)
{
    const float* x = (const float*)d_in[0];
    const float* y = (const float*)d_in[1];
    float* out = (float*)d_out;

    dim3 grid(GX, GY, GZ);
    ssim_fused_kernel<<<grid, NTHREADS, SMEM_BYTES>>>(x, y, out);
}